// round 14
// baseline (speedup 1.0000x reference)
#include <cuda_runtime.h>
#include <cuda_bf16.h>
#include <cuda_fp16.h>
#include <cstdint>

#define N_NODES 50000
#define N_EDGES 800000
#define DIM     128
#define NGRAPH  64

// ---------------- scratch (static device globals; no allocation) ----------------
__device__ __nv_bfloat16 g_Ahi[N_NODES * DIM];   // GEMM input (bf16)
__device__ __half        g_hw [N_NODES * DIM];   // GEMM output (SpMM gather input, fp16)
__device__ __nv_bfloat16 g_Whi[3 * DIM * DIM];   // W^T hi  [layer][n][k]
__device__ __nv_bfloat16 g_Wlo[3 * DIM * DIM];   // W^T lo  [layer][n][k]  (W error node-correlated -> split required)
__device__ int   g_deg[N_NODES];
__device__ float g_dinv[N_NODES];
__device__ int   g_off[N_NODES + 1];
__device__ int   g_cur[N_NODES];                 // preloaded with offsets by k_scan
__device__ int2  g_edge[N_EDGES];                // {src, norm bits} fused
__device__ int   g_is64;

// ---------------- small helpers ----------------
__device__ __forceinline__ int ldidx(const void* __restrict__ p, long long i) {
    if (g_is64) return (int)((const long long*)p)[i];
    return ((const int*)p)[i];
}
__device__ __forceinline__ uint32_t smem_u32(const void* p) {
    uint32_t a;
    asm("{ .reg .u64 t; cvta.to.shared.u64 t, %1; cvt.u32.u64 %0, t; }" : "=r"(a) : "l"(p));
    return a;
}
__device__ __forceinline__ uint32_t packbf2(float a, float b) {
    __nv_bfloat162 t = __floats2bfloat162_rn(a, b);
    return *reinterpret_cast<uint32_t*>(&t);
}
__device__ __forceinline__ float2 h2f2(uint32_t u) {
    __half2 h = *reinterpret_cast<__half2*>(&u);
    return __half22float2(h);
}

// ---------------- init: deg reset + dtype detect + W split + out zero (all fused) -------
__global__ void k_init(const int* __restrict__ probe, float* __restrict__ out,
                       const float* __restrict__ W0, const float* __restrict__ W1,
                       const float* __restrict__ W2) {
    int i = blockIdx.x * blockDim.x + threadIdx.x;
    if (i < N_NODES) g_deg[i] = 0;
    if (i < 3 * DIM * DIM) {
        int L = i >> 14;
        int idx = i & (DIM * DIM - 1);
        const float* W = (L == 0) ? W0 : (L == 1) ? W1 : W2;
        int k = idx >> 7, n = idx & 127;
        float v = W[idx];
        __nv_bfloat16 hi = __float2bfloat16_rn(v);
        float lo = v - __bfloat162float(hi);
        g_Whi[L * DIM * DIM + n * DIM + k] = hi;
        g_Wlo[L * DIM * DIM + n * DIM + k] = __float2bfloat16_rn(lo);
    }
    if (i < NGRAPH * DIM) out[i] = 0.f;
    if (blockIdx.x == 0) {
        __shared__ int nz;
        if (threadIdx.x == 0) nz = 0;
        __syncthreads();
        if (threadIdx.x < 256 && probe[threadIdx.x * 2 + 1] != 0) atomicAdd(&nz, 1);
        __syncthreads();
        if (threadIdx.x == 0) g_is64 = (nz == 0) ? 1 : 0;
    }
}

// 2 edges per thread, vectorized dst loads
__global__ void k_degree(const void* __restrict__ ei) {
    int t = blockIdx.x * blockDim.x + threadIdx.x;
    if (t >= N_EDGES / 2) return;
    int d0, d1;
    if (g_is64) {
        longlong2 v = ((const longlong2*)((const long long*)ei + N_EDGES))[t];
        d0 = (int)v.x; d1 = (int)v.y;
    } else {
        int2 v = ((const int2*)((const int*)ei + N_EDGES))[t];
        d0 = v.x; d1 = v.y;
    }
    atomicAdd(&g_deg[d0], 1);
    atomicAdd(&g_deg[d1], 1);
}

// scan; dinv fused; preloads g_cur with the running offset
__global__ void k_scan() {
    __shared__ int part[1024];
    const int CH = (N_NODES + 1023) / 1024;
    int t = threadIdx.x;
    int b = t * CH;
    int e = b + CH; if (e > N_NODES) e = N_NODES;
    int s = 0;
    for (int i = b; i < e; i++) {
        int d = g_deg[i];
        g_dinv[i] = rsqrtf((float)(d + 1));
        s += d;
    }
    part[t] = s;
    __syncthreads();
    for (int d = 1; d < 1024; d <<= 1) {
        int v = (t >= d) ? part[t - d] : 0;
        __syncthreads();
        part[t] += v;
        __syncthreads();
    }
    int run = (t > 0) ? part[t - 1] : 0;
    for (int i = b; i < e; i++) {
        g_off[i] = run;
        g_cur[i] = run;
        run += g_deg[i];
    }
    if (t == 1023) g_off[N_NODES] = part[1023];
}

// fill CSR (2 edges/thread, 1 atomic + 1 fused 8B store per edge)
__global__ void k_fill(const void* __restrict__ ei) {
    int t = blockIdx.x * blockDim.x + threadIdx.x;
    if (t >= N_EDGES / 2) return;
    int s0, s1, d0, d1;
    if (g_is64) {
        longlong2 sv = ((const longlong2*)ei)[t];
        longlong2 dv = ((const longlong2*)((const long long*)ei + N_EDGES))[t];
        s0 = (int)sv.x; s1 = (int)sv.y; d0 = (int)dv.x; d1 = (int)dv.y;
    } else {
        int2 sv = ((const int2*)ei)[t];
        int2 dv = ((const int2*)((const int*)ei + N_EDGES))[t];
        s0 = sv.x; s1 = sv.y; d0 = dv.x; d1 = dv.y;
    }
    float n0 = g_dinv[s0] * g_dinv[d0];
    float n1 = g_dinv[s1] * g_dinv[d1];
    int p0 = atomicAdd(&g_cur[d0], 1);
    int p1 = atomicAdd(&g_cur[d1], 1);
    g_edge[p0] = make_int2(s0, __float_as_int(n0));
    g_edge[p1] = make_int2(s1, __float_as_int(n1));
}

// ---------------- mma.sync GEMM: g_hw[m][n] = sum_k A[m][k] * W[k][n] ----------------
#define SAS 272
#define SM_AH 0
#define SM_WH (64 * SAS)
#define SM_WL (192 * SAS)
#define SM_TOT (320 * SAS)      // 87,040 B

__device__ __forceinline__ void ldsm4(uint32_t addr, uint32_t* r) {
    asm volatile("ldmatrix.sync.aligned.m8n8.x4.shared.b16 {%0,%1,%2,%3}, [%4];"
                 : "=r"(r[0]), "=r"(r[1]), "=r"(r[2]), "=r"(r[3]) : "r"(addr));
}
__device__ __forceinline__ void mma16816(float* d, const uint32_t* a, uint32_t b0, uint32_t b1) {
    asm volatile(
        "mma.sync.aligned.m16n8k16.row.col.f32.bf16.bf16.f32 "
        "{%0,%1,%2,%3}, {%4,%5,%6,%7}, {%8,%9}, {%0,%1,%2,%3};"
        : "+f"(d[0]), "+f"(d[1]), "+f"(d[2]), "+f"(d[3])
        : "r"(a[0]), "r"(a[1]), "r"(a[2]), "r"(a[3]), "r"(b0), "r"(b1));
}

__global__ void __launch_bounds__(128) k_gemm_mma(int layer, const float* __restrict__ xsrc) {
    extern __shared__ char smem[];
    uint32_t sb = smem_u32(smem);
    int tid = threadIdx.x, wid = tid >> 5, lane = tid & 31;
    int m0 = blockIdx.x * 64;
    int valid = N_NODES - m0; if (valid > 64) valid = 64;

    if (xsrc) {
        #pragma unroll
        for (int i = tid; i < 1024; i += 128) {
            int r = i >> 4, c = i & 15;
            uint4 vh = make_uint4(0, 0, 0, 0);
            if (r < valid) {
                const float4* xr = (const float4*)(xsrc + (long long)(m0 + r) * DIM) + c * 2;
                float4 f0 = xr[0], f1 = xr[1];
                vh.x = packbf2(f0.x, f0.y);
                vh.y = packbf2(f0.z, f0.w);
                vh.z = packbf2(f1.x, f1.y);
                vh.w = packbf2(f1.z, f1.w);
            }
            *(uint4*)(smem + SM_AH + r * SAS + c * 16) = vh;
        }
    } else {
        const uint4* gh = (const uint4*)(g_Ahi + (long long)m0 * DIM);
        #pragma unroll
        for (int i = tid; i < 1024; i += 128) {
            int r = i >> 4, c = i & 15;
            uint4 vh = make_uint4(0, 0, 0, 0);
            if (r < valid) vh = gh[r * 16 + c];
            *(uint4*)(smem + SM_AH + r * SAS + c * 16) = vh;
        }
    }
    {
        const uint4* wh = (const uint4*)(g_Whi + layer * DIM * DIM);
        const uint4* wl = (const uint4*)(g_Wlo + layer * DIM * DIM);
        #pragma unroll
        for (int i = tid; i < 2048; i += 128) {
            int r = i >> 4, c = i & 15;
            *(uint4*)(smem + SM_WH + r * SAS + c * 16) = wh[i];
            *(uint4*)(smem + SM_WL + r * SAS + c * 16) = wl[i];
        }
    }
    __syncthreads();

    float acc[16][4];
    #pragma unroll
    for (int j = 0; j < 16; j++)
        #pragma unroll
        for (int q = 0; q < 4; q++) acc[j][q] = 0.f;

    int wm = wid * 16;
    uint32_t a_off = (uint32_t)((wm + (lane & 15)) * SAS + ((lane >> 4) << 3) * 2);
    uint32_t b_off = (uint32_t)(((lane & 7) + ((lane >> 4) << 3)) * SAS + (((lane >> 3) & 1) << 3) * 2);

    for (int kk = 0; kk < 8; kk++) {
        uint32_t kb = kk * 32;
        uint32_t ah[4];
        ldsm4(sb + SM_AH + a_off + kb, ah);
        #pragma unroll
        for (int nt = 0; nt < 8; nt++) {
            uint32_t bh[4], bl[4];
            uint32_t nrow = nt * 16 * SAS;
            ldsm4(sb + SM_WH + nrow + b_off + kb, bh);
            ldsm4(sb + SM_WL + nrow + b_off + kb, bl);
            mma16816(acc[2 * nt],     ah, bh[0], bh[1]);
            mma16816(acc[2 * nt + 1], ah, bh[2], bh[3]);
            mma16816(acc[2 * nt],     ah, bl[0], bl[1]);
            mma16816(acc[2 * nt + 1], ah, bl[2], bl[3]);
        }
    }

    int r0 = m0 + wm + (lane >> 2);
    int cb = (lane & 3) * 2;
    if (r0 < N_NODES) {
        __half* d = g_hw + (long long)r0 * DIM;
        #pragma unroll
        for (int j = 0; j < 16; j++)
            *(__half2*)(d + j * 8 + cb) = __floats2half2_rn(acc[j][0], acc[j][1]);
    }
    if (r0 + 8 < N_NODES) {
        __half* d = g_hw + (long long)(r0 + 8) * DIM;
        #pragma unroll
        for (int j = 0; j < 16; j++)
            *(__half2*)(d + j * 8 + cb) = __floats2half2_rn(acc[j][2], acc[j][3]);
    }
}

// ---------------- SpMM: fp16 gather, fused edges, relu; out = bf16 OR pooled atomicAdd ----
__device__ __forceinline__ void acc_edge(float4& acc, float n, uint2 v) {
    float2 a = h2f2(v.x), b = h2f2(v.y);
    acc.x += n * a.x; acc.y += n * a.y; acc.z += n * b.x; acc.w += n * b.y;
}

__global__ void __launch_bounds__(256) k_spmm(const float* __restrict__ bias,
                                              const void* __restrict__ batch,
                                              float* __restrict__ pool_out) {
    int warp = (blockIdx.x * blockDim.x + threadIdx.x) >> 5;
    int lane = threadIdx.x & 31;
    if (warp >= N_NODES) return;
    int i = warp;

    float di = g_dinv[i];
    float sl = di * di;
    float4 acc;
    {
        uint2 v = ((const uint2*)(g_hw + (long long)i * DIM))[lane];
        float2 a = h2f2(v.x), b = h2f2(v.y);
        acc = make_float4(sl * a.x, sl * a.y, sl * b.x, sl * b.y);
    }

    int p = g_off[i], pe = g_off[i + 1];
    for (; p + 4 <= pe; p += 4) {
        int2 e0 = g_edge[p],     e1 = g_edge[p + 1];
        int2 e2 = g_edge[p + 2], e3 = g_edge[p + 3];
        uint2 v0 = ((const uint2*)(g_hw + (long long)e0.x * DIM))[lane];
        uint2 v1 = ((const uint2*)(g_hw + (long long)e1.x * DIM))[lane];
        uint2 v2 = ((const uint2*)(g_hw + (long long)e2.x * DIM))[lane];
        uint2 v3 = ((const uint2*)(g_hw + (long long)e3.x * DIM))[lane];
        acc_edge(acc, __int_as_float(e0.y), v0);
        acc_edge(acc, __int_as_float(e1.y), v1);
        acc_edge(acc, __int_as_float(e2.y), v2);
        acc_edge(acc, __int_as_float(e3.y), v3);
    }
    for (; p < pe; p++) {
        int2 e = g_edge[p];
        uint2 v = ((const uint2*)(g_hw + (long long)e.x * DIM))[lane];
        acc_edge(acc, __int_as_float(e.y), v);
    }

    float4 bv = ((const float4*)bias)[lane];
    acc.x = fmaxf(acc.x + bv.x, 0.f);
    acc.y = fmaxf(acc.y + bv.y, 0.f);
    acc.z = fmaxf(acc.z + bv.z, 0.f);
    acc.w = fmaxf(acc.w + bv.w, 0.f);

    if (pool_out) {
        // last layer: pool directly into out[g][*] (zeroed by k_init)
        int g = ldidx(batch, i);
        float* dst = pool_out + g * DIM + lane * 4;
        atomicAdd(dst + 0, acc.x);
        atomicAdd(dst + 1, acc.y);
        atomicAdd(dst + 2, acc.z);
        atomicAdd(dst + 3, acc.w);
    } else {
        uint2 ph;
        ph.x = packbf2(acc.x, acc.y);
        ph.y = packbf2(acc.z, acc.w);
        ((uint2*)g_Ahi)[(long long)i * 32 + lane] = ph;
    }
}

// ---------------- pool divide (counts via binary search on sorted batch) ----------------
__device__ __forceinline__ int lbound(const void* __restrict__ b, int key) {
    int lo = 0, hi = N_NODES;
    while (lo < hi) {
        int mid = (lo + hi) >> 1;
        if (ldidx(b, mid) < key) lo = mid + 1; else hi = mid;
    }
    return lo;
}
__global__ void k_pool_div(const void* __restrict__ batch, float* __restrict__ out) {
    int g = blockIdx.x;
    int t = threadIdx.x;
    int start = lbound(batch, g);
    int end   = lbound(batch, g + 1);
    float cnt = (float)(end - start);
    if (cnt < 1.f) cnt = 1.f;
    out[g * DIM + t] /= cnt;
}

// ---------------- launch (single stream; fork removed — it starved k_scan) -------------
extern "C" void kernel_launch(void* const* d_in, const int* in_sizes, int n_in,
                              void* d_out, int out_size) {
    (void)out_size;
    const float* x = 0; const void* ei = 0; const void* batch = 0;
    const float* W[3] = {0, 0, 0}; const float* b[3] = {0, 0, 0};
    int nw = 0, nb = 0;
    for (int i = 0; i < n_in; i++) {
        int sz = in_sizes[i];
        if      (sz == N_NODES * DIM) x     = (const float*)d_in[i];
        else if (sz == 2 * N_EDGES)   ei    = d_in[i];
        else if (sz == N_NODES)       batch = d_in[i];
        else if (sz == DIM * DIM)     { if (nw < 3) W[nw++] = (const float*)d_in[i]; }
        else if (sz == DIM)           { if (nb < 3) b[nb++] = (const float*)d_in[i]; }
    }
    float* out = (float*)d_out;

    cudaFuncSetAttribute(k_gemm_mma, cudaFuncAttributeMaxDynamicSharedMemorySize, SM_TOT);

    const int NT = 256;
    int nblk = (N_NODES + NT - 1) / NT;
    int e2blk = (N_EDGES / 2 + NT - 1) / NT;
    int spmm_blocks = (N_NODES * 32 + NT - 1) / NT;
    int gemm_blocks = (N_NODES + 63) / 64;  // 782

    // preprocess (4 launches; init also splits W + zeros out)
    k_init<<<nblk, NT>>>((const int*)ei, out, W[0], W[1], W[2]);
    k_degree<<<e2blk, NT>>>(ei);
    k_scan<<<1, 1024>>>();
    k_fill<<<e2blk, NT>>>(ei);

    // layers (6 launches); layer 0 stages bf16(x); layer 2 pools directly
    k_gemm_mma<<<gemm_blocks, 128, SM_TOT>>>(0, x);
    k_spmm<<<spmm_blocks, NT>>>(b[0], batch, nullptr);
    k_gemm_mma<<<gemm_blocks, 128, SM_TOT>>>(1, nullptr);
    k_spmm<<<spmm_blocks, NT>>>(b[1], batch, nullptr);
    k_gemm_mma<<<gemm_blocks, 128, SM_TOT>>>(2, nullptr);
    k_spmm<<<spmm_blocks, NT>>>(b[2], batch, out);   // fused pool

    k_pool_div<<<NGRAPH, DIM>>>(batch, out);
}

// round 15
// speedup vs baseline: 1.3952x; 1.3952x over previous
#include <cuda_runtime.h>
#include <cuda_bf16.h>
#include <cuda_fp16.h>
#include <cstdint>

#define N_NODES 50000
#define N_EDGES 800000
#define DIM     128
#define NGRAPH  64

// ---------------- scratch (static device globals; no allocation) ----------------
__device__ __nv_bfloat16 g_Ahi[N_NODES * DIM];   // GEMM input (bf16); also pool source
__device__ int           g_q  [N_NODES * 32];    // GEMM output, int8 rows (32 x int32 per row)
__device__ float         g_rsc[N_NODES];         // per-row dequant scale
__device__ __nv_bfloat16 g_Whi[3 * DIM * DIM];   // W^T hi  [layer][n][k]
__device__ __nv_bfloat16 g_Wlo[3 * DIM * DIM];   // W^T lo  [layer][n][k]  (W error node-correlated -> split required)
__device__ int   g_deg[N_NODES];
__device__ float g_dinv[N_NODES];
__device__ int   g_off[N_NODES + 1];
__device__ int   g_cur[N_NODES];                 // preloaded with offsets by k_scan
__device__ int2  g_edge[N_EDGES];                // {src, norm bits} fused
__device__ int   g_is64;
#define PCH 16
__device__ float g_pool[PCH * NGRAPH * DIM];

// ---------------- small helpers ----------------
__device__ __forceinline__ int ldidx(const void* __restrict__ p, long long i) {
    if (g_is64) return (int)((const long long*)p)[i];
    return ((const int*)p)[i];
}
__device__ __forceinline__ uint32_t smem_u32(const void* p) {
    uint32_t a;
    asm("{ .reg .u64 t; cvta.to.shared.u64 t, %1; cvt.u32.u64 %0, t; }" : "=r"(a) : "l"(p));
    return a;
}
__device__ __forceinline__ uint32_t packbf2(float a, float b) {
    __nv_bfloat162 t = __floats2bfloat162_rn(a, b);
    return *reinterpret_cast<uint32_t*>(&t);
}

// ---------------- init: deg reset + dtype detect + W split (fused) ----------------
__global__ void k_init(const int* __restrict__ probe,
                       const float* __restrict__ W0, const float* __restrict__ W1,
                       const float* __restrict__ W2) {
    int i = blockIdx.x * blockDim.x + threadIdx.x;
    if (i < N_NODES) g_deg[i] = 0;
    if (i < 3 * DIM * DIM) {
        int L = i >> 14;
        int idx = i & (DIM * DIM - 1);
        const float* W = (L == 0) ? W0 : (L == 1) ? W1 : W2;
        int k = idx >> 7, n = idx & 127;
        float v = W[idx];
        __nv_bfloat16 hi = __float2bfloat16_rn(v);
        float lo = v - __bfloat162float(hi);
        g_Whi[L * DIM * DIM + n * DIM + k] = hi;
        g_Wlo[L * DIM * DIM + n * DIM + k] = __float2bfloat16_rn(lo);
    }
    if (blockIdx.x == 0) {
        __shared__ int nz;
        if (threadIdx.x == 0) nz = 0;
        __syncthreads();
        if (threadIdx.x < 256 && probe[threadIdx.x * 2 + 1] != 0) atomicAdd(&nz, 1);
        __syncthreads();
        if (threadIdx.x == 0) g_is64 = (nz == 0) ? 1 : 0;
    }
}

// 2 edges per thread, vectorized dst loads
__global__ void k_degree(const void* __restrict__ ei) {
    int t = blockIdx.x * blockDim.x + threadIdx.x;
    if (t >= N_EDGES / 2) return;
    int d0, d1;
    if (g_is64) {
        longlong2 v = ((const longlong2*)((const long long*)ei + N_EDGES))[t];
        d0 = (int)v.x; d1 = (int)v.y;
    } else {
        int2 v = ((const int2*)((const int*)ei + N_EDGES))[t];
        d0 = v.x; d1 = v.y;
    }
    atomicAdd(&g_deg[d0], 1);
    atomicAdd(&g_deg[d1], 1);
}

// scan; dinv fused; preloads g_cur with the running offset
__global__ void k_scan() {
    __shared__ int part[1024];
    const int CH = (N_NODES + 1023) / 1024;
    int t = threadIdx.x;
    int b = t * CH;
    int e = b + CH; if (e > N_NODES) e = N_NODES;
    int s = 0;
    for (int i = b; i < e; i++) {
        int d = g_deg[i];
        g_dinv[i] = rsqrtf((float)(d + 1));
        s += d;
    }
    part[t] = s;
    __syncthreads();
    for (int d = 1; d < 1024; d <<= 1) {
        int v = (t >= d) ? part[t - d] : 0;
        __syncthreads();
        part[t] += v;
        __syncthreads();
    }
    int run = (t > 0) ? part[t - 1] : 0;
    for (int i = b; i < e; i++) {
        g_off[i] = run;
        g_cur[i] = run;
        run += g_deg[i];
    }
    if (t == 1023) g_off[N_NODES] = part[1023];
}

// fill CSR (2 edges/thread, 1 atomic + 1 fused 8B store per edge)
__global__ void k_fill(const void* __restrict__ ei) {
    int t = blockIdx.x * blockDim.x + threadIdx.x;
    if (t >= N_EDGES / 2) return;
    int s0, s1, d0, d1;
    if (g_is64) {
        longlong2 sv = ((const longlong2*)ei)[t];
        longlong2 dv = ((const longlong2*)((const long long*)ei + N_EDGES))[t];
        s0 = (int)sv.x; s1 = (int)sv.y; d0 = (int)dv.x; d1 = (int)dv.y;
    } else {
        int2 sv = ((const int2*)ei)[t];
        int2 dv = ((const int2*)((const int*)ei + N_EDGES))[t];
        s0 = sv.x; s1 = sv.y; d0 = dv.x; d1 = dv.y;
    }
    float n0 = g_dinv[s0] * g_dinv[d0];
    float n1 = g_dinv[s1] * g_dinv[d1];
    int p0 = atomicAdd(&g_cur[d0], 1);
    int p1 = atomicAdd(&g_cur[d1], 1);
    g_edge[p0] = make_int2(s0, __float_as_int(n0));
    g_edge[p1] = make_int2(s1, __float_as_int(n1));
}

// ---------------- mma.sync GEMM -> per-row int8 quantized output ----------------
#define SAS 272
#define SM_AH 0
#define SM_WH (64 * SAS)
#define SM_WL (192 * SAS)
#define SM_TOT (320 * SAS)      // 87,040 B

__device__ __forceinline__ void ldsm4(uint32_t addr, uint32_t* r) {
    asm volatile("ldmatrix.sync.aligned.m8n8.x4.shared.b16 {%0,%1,%2,%3}, [%4];"
                 : "=r"(r[0]), "=r"(r[1]), "=r"(r[2]), "=r"(r[3]) : "r"(addr));
}
__device__ __forceinline__ void mma16816(float* d, const uint32_t* a, uint32_t b0, uint32_t b1) {
    asm volatile(
        "mma.sync.aligned.m16n8k16.row.col.f32.bf16.bf16.f32 "
        "{%0,%1,%2,%3}, {%4,%5,%6,%7}, {%8,%9}, {%0,%1,%2,%3};"
        : "+f"(d[0]), "+f"(d[1]), "+f"(d[2]), "+f"(d[3])
        : "r"(a[0]), "r"(a[1]), "r"(a[2]), "r"(a[3]), "r"(b0), "r"(b1));
}

__global__ void __launch_bounds__(128) k_gemm_mma(int layer, const float* __restrict__ xsrc) {
    extern __shared__ char smem[];
    uint32_t sb = smem_u32(smem);
    int tid = threadIdx.x, wid = tid >> 5, lane = tid & 31;
    int m0 = blockIdx.x * 64;
    int valid = N_NODES - m0; if (valid > 64) valid = 64;

    if (xsrc) {
        #pragma unroll
        for (int i = tid; i < 1024; i += 128) {
            int r = i >> 4, c = i & 15;
            uint4 vh = make_uint4(0, 0, 0, 0);
            if (r < valid) {
                const float4* xr = (const float4*)(xsrc + (long long)(m0 + r) * DIM) + c * 2;
                float4 f0 = xr[0], f1 = xr[1];
                vh.x = packbf2(f0.x, f0.y);
                vh.y = packbf2(f0.z, f0.w);
                vh.z = packbf2(f1.x, f1.y);
                vh.w = packbf2(f1.z, f1.w);
            }
            *(uint4*)(smem + SM_AH + r * SAS + c * 16) = vh;
        }
    } else {
        const uint4* gh = (const uint4*)(g_Ahi + (long long)m0 * DIM);
        #pragma unroll
        for (int i = tid; i < 1024; i += 128) {
            int r = i >> 4, c = i & 15;
            uint4 vh = make_uint4(0, 0, 0, 0);
            if (r < valid) vh = gh[r * 16 + c];
            *(uint4*)(smem + SM_AH + r * SAS + c * 16) = vh;
        }
    }
    {
        const uint4* wh = (const uint4*)(g_Whi + layer * DIM * DIM);
        const uint4* wl = (const uint4*)(g_Wlo + layer * DIM * DIM);
        #pragma unroll
        for (int i = tid; i < 2048; i += 128) {
            int r = i >> 4, c = i & 15;
            *(uint4*)(smem + SM_WH + r * SAS + c * 16) = wh[i];
            *(uint4*)(smem + SM_WL + r * SAS + c * 16) = wl[i];
        }
    }
    __syncthreads();

    float acc[16][4];
    #pragma unroll
    for (int j = 0; j < 16; j++)
        #pragma unroll
        for (int q = 0; q < 4; q++) acc[j][q] = 0.f;

    int wm = wid * 16;
    uint32_t a_off = (uint32_t)((wm + (lane & 15)) * SAS + ((lane >> 4) << 3) * 2);
    uint32_t b_off = (uint32_t)(((lane & 7) + ((lane >> 4) << 3)) * SAS + (((lane >> 3) & 1) << 3) * 2);

    for (int kk = 0; kk < 8; kk++) {
        uint32_t kb = kk * 32;
        uint32_t ah[4];
        ldsm4(sb + SM_AH + a_off + kb, ah);
        #pragma unroll
        for (int nt = 0; nt < 8; nt++) {
            uint32_t bh[4], bl[4];
            uint32_t nrow = nt * 16 * SAS;
            ldsm4(sb + SM_WH + nrow + b_off + kb, bh);
            ldsm4(sb + SM_WL + nrow + b_off + kb, bl);
            mma16816(acc[2 * nt],     ah, bh[0], bh[1]);
            mma16816(acc[2 * nt + 1], ah, bh[2], bh[3]);
            mma16816(acc[2 * nt],     ah, bl[0], bl[1]);
            mma16816(acc[2 * nt + 1], ah, bl[2], bl[3]);
        }
    }

    // ---- epilogue: per-row symmetric int8 quantization (layout validated in R11) ----
    int r0 = m0 + wm + (lane >> 2);
    int cb = (lane & 3) * 2;

    float m0v = 0.f, m1v = 0.f;
    #pragma unroll
    for (int j = 0; j < 16; j++) {
        m0v = fmaxf(m0v, fmaxf(fabsf(acc[j][0]), fabsf(acc[j][1])));
        m1v = fmaxf(m1v, fmaxf(fabsf(acc[j][2]), fabsf(acc[j][3])));
    }
    m0v = fmaxf(m0v, __shfl_xor_sync(0xffffffffu, m0v, 1));
    m0v = fmaxf(m0v, __shfl_xor_sync(0xffffffffu, m0v, 2));
    m1v = fmaxf(m1v, __shfl_xor_sync(0xffffffffu, m1v, 1));
    m1v = fmaxf(m1v, __shfl_xor_sync(0xffffffffu, m1v, 2));
    float i0 = (m0v > 0.f) ? 127.f / m0v : 0.f;
    float i1 = (m1v > 0.f) ? 127.f / m1v : 0.f;
    if ((lane & 3) == 0) {
        if (r0 < N_NODES)     g_rsc[r0]     = m0v * (1.f / 127.f);
        if (r0 + 8 < N_NODES) g_rsc[r0 + 8] = m1v * (1.f / 127.f);
    }
    if (r0 < N_NODES) {
        unsigned short* d = (unsigned short*)((char*)g_q + (long long)r0 * DIM) + (cb >> 1);
        #pragma unroll
        for (int j = 0; j < 16; j++) {
            int q0 = __float2int_rn(acc[j][0] * i0);
            int q1 = __float2int_rn(acc[j][1] * i0);
            d[j * 4] = (unsigned short)((q0 & 0xff) | ((q1 & 0xff) << 8));
        }
    }
    if (r0 + 8 < N_NODES) {
        unsigned short* d = (unsigned short*)((char*)g_q + (long long)(r0 + 8) * DIM) + (cb >> 1);
        #pragma unroll
        for (int j = 0; j < 16; j++) {
            int q0 = __float2int_rn(acc[j][2] * i1);
            int q1 = __float2int_rn(acc[j][3] * i1);
            d[j * 4] = (unsigned short)((q0 & 0xff) | ((q1 & 0xff) << 8));
        }
    }
}

// ---------------- SpMM: int8 gather (4B/lane), PRMT magic dequant, relu, bf16 out ----
#define MAGIC_F 8388736.0f   // as_float(0x4B000000 | 0x80) : 2^23 + 128

__device__ __forceinline__ void acc_q(float4& a, float c, int w) {
    uint32_t u = (uint32_t)w ^ 0x80808080u;
    float f0 = __uint_as_float(__byte_perm(u, 0x4B000000u, 0x7540)) - MAGIC_F;
    float f1 = __uint_as_float(__byte_perm(u, 0x4B000000u, 0x7541)) - MAGIC_F;
    float f2 = __uint_as_float(__byte_perm(u, 0x4B000000u, 0x7542)) - MAGIC_F;
    float f3 = __uint_as_float(__byte_perm(u, 0x4B000000u, 0x7543)) - MAGIC_F;
    a.x += c * f0; a.y += c * f1; a.z += c * f2; a.w += c * f3;
}

__global__ void __launch_bounds__(256) k_spmm(const float* __restrict__ bias) {
    int warp = (blockIdx.x * blockDim.x + threadIdx.x) >> 5;
    int lane = threadIdx.x & 31;
    if (warp >= N_NODES) return;
    int i = warp;

    float di = g_dinv[i];
    float4 acc = make_float4(0.f, 0.f, 0.f, 0.f);
    {
        float c = di * di * g_rsc[i];
        acc_q(acc, c, g_q[i * 32 + lane]);
    }

    int p = g_off[i], pe = g_off[i + 1];
    for (; p + 4 <= pe; p += 4) {
        int2 e0 = g_edge[p],     e1 = g_edge[p + 1];
        int2 e2 = g_edge[p + 2], e3 = g_edge[p + 3];
        float c0 = __int_as_float(e0.y) * g_rsc[e0.x];
        float c1 = __int_as_float(e1.y) * g_rsc[e1.x];
        float c2 = __int_as_float(e2.y) * g_rsc[e2.x];
        float c3 = __int_as_float(e3.y) * g_rsc[e3.x];
        int w0 = g_q[e0.x * 32 + lane];
        int w1 = g_q[e1.x * 32 + lane];
        int w2 = g_q[e2.x * 32 + lane];
        int w3 = g_q[e3.x * 32 + lane];
        acc_q(acc, c0, w0);
        acc_q(acc, c1, w1);
        acc_q(acc, c2, w2);
        acc_q(acc, c3, w3);
    }
    for (; p < pe; p++) {
        int2 e = g_edge[p];
        float c = __int_as_float(e.y) * g_rsc[e.x];
        acc_q(acc, c, g_q[e.x * 32 + lane]);
    }

    float4 bv = ((const float4*)bias)[lane];
    acc.x = fmaxf(acc.x + bv.x, 0.f);
    acc.y = fmaxf(acc.y + bv.y, 0.f);
    acc.z = fmaxf(acc.z + bv.z, 0.f);
    acc.w = fmaxf(acc.w + bv.w, 0.f);

    uint2 ph;
    ph.x = packbf2(acc.x, acc.y);
    ph.y = packbf2(acc.z, acc.w);
    ((uint2*)g_Ahi)[(long long)i * 32 + lane] = ph;
}

// ---------------- global mean pool (partial sums; NO atomics — hot-address atomics cost 140us) ----
__device__ __forceinline__ int lbound(const void* __restrict__ b, int key) {
    int lo = 0, hi = N_NODES;
    while (lo < hi) {
        int mid = (lo + hi) >> 1;
        if (ldidx(b, mid) < key) lo = mid + 1; else hi = mid;
    }
    return lo;
}
__global__ void k_pool(const void* __restrict__ batch) {
    int g = blockIdx.x / PCH;
    int c = blockIdx.x % PCH;
    int t = threadIdx.x;
    int start = lbound(batch, g);
    int end   = lbound(batch, g + 1);
    int len = end - start;
    int rs = start + (int)((long long)len * c / PCH);
    int re = start + (int)((long long)len * (c + 1) / PCH);
    float s = 0.f;
    for (int r = rs; r < re; r++)
        s += __bfloat162float(g_Ahi[(long long)r * DIM + t]);
    g_pool[(c * NGRAPH + g) * DIM + t] = s;
}
__global__ void k_pool_div(const void* __restrict__ batch, float* __restrict__ out) {
    int g = blockIdx.x;
    int t = threadIdx.x;
    float s = 0.f;
    #pragma unroll
    for (int c = 0; c < PCH; c++) s += g_pool[(c * NGRAPH + g) * DIM + t];
    int start = lbound(batch, g);
    int end   = lbound(batch, g + 1);
    float cnt = (float)(end - start);
    if (cnt < 1.f) cnt = 1.f;
    out[g * DIM + t] = s / cnt;
}

// ---------------- launch (single stream) ----------------
extern "C" void kernel_launch(void* const* d_in, const int* in_sizes, int n_in,
                              void* d_out, int out_size) {
    (void)out_size;
    const float* x = 0; const void* ei = 0; const void* batch = 0;
    const float* W[3] = {0, 0, 0}; const float* b[3] = {0, 0, 0};
    int nw = 0, nb = 0;
    for (int i = 0; i < n_in; i++) {
        int sz = in_sizes[i];
        if      (sz == N_NODES * DIM) x     = (const float*)d_in[i];
        else if (sz == 2 * N_EDGES)   ei    = d_in[i];
        else if (sz == N_NODES)       batch = d_in[i];
        else if (sz == DIM * DIM)     { if (nw < 3) W[nw++] = (const float*)d_in[i]; }
        else if (sz == DIM)           { if (nb < 3) b[nb++] = (const float*)d_in[i]; }
    }
    float* out = (float*)d_out;

    cudaFuncSetAttribute(k_gemm_mma, cudaFuncAttributeMaxDynamicSharedMemorySize, SM_TOT);

    const int NT = 256;
    int nblk = (N_NODES + NT - 1) / NT;
    int e2blk = (N_EDGES / 2 + NT - 1) / NT;
    int spmm_blocks = (N_NODES * 32 + NT - 1) / NT;
    int gemm_blocks = (N_NODES + 63) / 64;  // 782

    // preprocess (4 launches; init also splits W)
    k_init<<<nblk, NT>>>((const int*)ei, W[0], W[1], W[2]);
    k_degree<<<e2blk, NT>>>(ei);
    k_scan<<<1, 1024>>>();
    k_fill<<<e2blk, NT>>>(ei);

    // layers (6 launches); layer 0 stages bf16(x) directly
    k_gemm_mma<<<gemm_blocks, 128, SM_TOT>>>(0, x);
    k_spmm<<<spmm_blocks, NT>>>(b[0]);
    k_gemm_mma<<<gemm_blocks, 128, SM_TOT>>>(1, nullptr);
    k_spmm<<<spmm_blocks, NT>>>(b[1]);
    k_gemm_mma<<<gemm_blocks, 128, SM_TOT>>>(2, nullptr);
    k_spmm<<<spmm_blocks, NT>>>(b[2]);

    // pool (2 launches, partial sums)
    k_pool<<<NGRAPH * PCH, DIM>>>(batch);
    k_pool_div<<<NGRAPH, DIM>>>(batch, out);
}

// round 16
// speedup vs baseline: 1.5448x; 1.1072x over previous
#include <cuda_runtime.h>
#include <cuda_bf16.h>
#include <cuda_fp16.h>
#include <cstdint>

#define N_NODES 50000
#define N_EDGES 800000
#define DIM     128
#define NGRAPH  64

// ---------------- scratch (static device globals; no allocation) ----------------
__device__ __nv_bfloat16 g_Ahi[N_NODES * DIM];   // GEMM input (bf16); also pool source
__device__ __half        g_hw [N_NODES * DIM];   // GEMM output (SpMM gather input, fp16)
__device__ __nv_bfloat16 g_Whi[3 * DIM * DIM];   // W^T hi  [layer][n][k]
__device__ __nv_bfloat16 g_Wlo[3 * DIM * DIM];   // W^T lo  [layer][n][k]  (W error node-correlated -> split required)
__device__ int   g_deg[N_NODES];
__device__ float g_dinv[N_NODES];
__device__ int   g_off[N_NODES + 1];
__device__ int   g_cur[N_NODES];                 // preloaded with offsets by k_scan
__device__ int2  g_edge[N_EDGES];                // {src, norm bits} fused
__device__ int   g_is64;
#define PCH 16
__device__ float g_pool[PCH * NGRAPH * DIM];

// ---------------- small helpers ----------------
__device__ __forceinline__ int ldidx(const void* __restrict__ p, long long i) {
    if (g_is64) return (int)((const long long*)p)[i];
    return ((const int*)p)[i];
}
__device__ __forceinline__ uint32_t smem_u32(const void* p) {
    uint32_t a;
    asm("{ .reg .u64 t; cvta.to.shared.u64 t, %1; cvt.u32.u64 %0, t; }" : "=r"(a) : "l"(p));
    return a;
}
__device__ __forceinline__ uint32_t packbf2(float a, float b) {
    __nv_bfloat162 t = __floats2bfloat162_rn(a, b);
    return *reinterpret_cast<uint32_t*>(&t);
}
__device__ __forceinline__ float2 h2f2(uint32_t u) {
    __half2 h = *reinterpret_cast<__half2*>(&u);
    return __half22float2(h);
}

// ---------------- init: deg reset + dtype detect + W split (fused) ----------------
__global__ void k_init(const int* __restrict__ probe,
                       const float* __restrict__ W0, const float* __restrict__ W1,
                       const float* __restrict__ W2) {
    int i = blockIdx.x * blockDim.x + threadIdx.x;
    if (i < N_NODES) g_deg[i] = 0;
    if (i < 3 * DIM * DIM) {
        int L = i >> 14;
        int idx = i & (DIM * DIM - 1);
        const float* W = (L == 0) ? W0 : (L == 1) ? W1 : W2;
        int k = idx >> 7, n = idx & 127;
        float v = W[idx];
        __nv_bfloat16 hi = __float2bfloat16_rn(v);
        float lo = v - __bfloat162float(hi);
        g_Whi[L * DIM * DIM + n * DIM + k] = hi;
        g_Wlo[L * DIM * DIM + n * DIM + k] = __float2bfloat16_rn(lo);
    }
    if (blockIdx.x == 0) {
        __shared__ int nz;
        if (threadIdx.x == 0) nz = 0;
        __syncthreads();
        if (threadIdx.x < 256 && probe[threadIdx.x * 2 + 1] != 0) atomicAdd(&nz, 1);
        __syncthreads();
        if (threadIdx.x == 0) g_is64 = (nz == 0) ? 1 : 0;
    }
}

// 2 edges per thread, vectorized dst loads
__global__ void k_degree(const void* __restrict__ ei) {
    int t = blockIdx.x * blockDim.x + threadIdx.x;
    if (t >= N_EDGES / 2) return;
    int d0, d1;
    if (g_is64) {
        longlong2 v = ((const longlong2*)((const long long*)ei + N_EDGES))[t];
        d0 = (int)v.x; d1 = (int)v.y;
    } else {
        int2 v = ((const int2*)((const int*)ei + N_EDGES))[t];
        d0 = v.x; d1 = v.y;
    }
    atomicAdd(&g_deg[d0], 1);
    atomicAdd(&g_deg[d1], 1);
}

// scan; dinv fused; preloads g_cur with the running offset. Runs ALONE on the chip.
__global__ void k_scan() {
    __shared__ int part[1024];
    const int CH = (N_NODES + 1023) / 1024;
    int t = threadIdx.x;
    int b = t * CH;
    int e = b + CH; if (e > N_NODES) e = N_NODES;
    int s = 0;
    for (int i = b; i < e; i++) {
        int d = g_deg[i];
        g_dinv[i] = rsqrtf((float)(d + 1));
        s += d;
    }
    part[t] = s;
    __syncthreads();
    for (int d = 1; d < 1024; d <<= 1) {
        int v = (t >= d) ? part[t - d] : 0;
        __syncthreads();
        part[t] += v;
        __syncthreads();
    }
    int run = (t > 0) ? part[t - 1] : 0;
    for (int i = b; i < e; i++) {
        g_off[i] = run;
        g_cur[i] = run;
        run += g_deg[i];
    }
    if (t == 1023) g_off[N_NODES] = part[1023];
}

// fill CSR (2 edges/thread, 1 atomic + 1 fused 8B store per edge)
__global__ void k_fill(const void* __restrict__ ei) {
    int t = blockIdx.x * blockDim.x + threadIdx.x;
    if (t >= N_EDGES / 2) return;
    int s0, s1, d0, d1;
    if (g_is64) {
        longlong2 sv = ((const longlong2*)ei)[t];
        longlong2 dv = ((const longlong2*)((const long long*)ei + N_EDGES))[t];
        s0 = (int)sv.x; s1 = (int)sv.y; d0 = (int)dv.x; d1 = (int)dv.y;
    } else {
        int2 sv = ((const int2*)ei)[t];
        int2 dv = ((const int2*)((const int*)ei + N_EDGES))[t];
        s0 = sv.x; s1 = sv.y; d0 = dv.x; d1 = dv.y;
    }
    float n0 = g_dinv[s0] * g_dinv[d0];
    float n1 = g_dinv[s1] * g_dinv[d1];
    int p0 = atomicAdd(&g_cur[d0], 1);
    int p1 = atomicAdd(&g_cur[d1], 1);
    g_edge[p0] = make_int2(s0, __float_as_int(n0));
    g_edge[p1] = make_int2(s1, __float_as_int(n1));
}

// ---------------- mma.sync GEMM: g_hw[m][n] = sum_k A[m][k] * W[k][n] ----------------
#define SAS 272
#define SM_AH 0
#define SM_WH (64 * SAS)
#define SM_WL (192 * SAS)
#define SM_TOT (320 * SAS)      // 87,040 B

__device__ __forceinline__ void ldsm4(uint32_t addr, uint32_t* r) {
    asm volatile("ldmatrix.sync.aligned.m8n8.x4.shared.b16 {%0,%1,%2,%3}, [%4];"
                 : "=r"(r[0]), "=r"(r[1]), "=r"(r[2]), "=r"(r[3]) : "r"(addr));
}
__device__ __forceinline__ void mma16816(float* d, const uint32_t* a, uint32_t b0, uint32_t b1) {
    asm volatile(
        "mma.sync.aligned.m16n8k16.row.col.f32.bf16.bf16.f32 "
        "{%0,%1,%2,%3}, {%4,%5,%6,%7}, {%8,%9}, {%0,%1,%2,%3};"
        : "+f"(d[0]), "+f"(d[1]), "+f"(d[2]), "+f"(d[3])
        : "r"(a[0]), "r"(a[1]), "r"(a[2]), "r"(a[3]), "r"(b0), "r"(b1));
}

__global__ void __launch_bounds__(128) k_gemm_mma(int layer, const float* __restrict__ xsrc) {
    extern __shared__ char smem[];
    uint32_t sb = smem_u32(smem);
    int tid = threadIdx.x, wid = tid >> 5, lane = tid & 31;
    int m0 = blockIdx.x * 64;
    int valid = N_NODES - m0; if (valid > 64) valid = 64;

    if (xsrc) {
        #pragma unroll
        for (int i = tid; i < 1024; i += 128) {
            int r = i >> 4, c = i & 15;
            uint4 vh = make_uint4(0, 0, 0, 0);
            if (r < valid) {
                const float4* xr = (const float4*)(xsrc + (long long)(m0 + r) * DIM) + c * 2;
                float4 f0 = xr[0], f1 = xr[1];
                vh.x = packbf2(f0.x, f0.y);
                vh.y = packbf2(f0.z, f0.w);
                vh.z = packbf2(f1.x, f1.y);
                vh.w = packbf2(f1.z, f1.w);
            }
            *(uint4*)(smem + SM_AH + r * SAS + c * 16) = vh;
        }
    } else {
        const uint4* gh = (const uint4*)(g_Ahi + (long long)m0 * DIM);
        #pragma unroll
        for (int i = tid; i < 1024; i += 128) {
            int r = i >> 4, c = i & 15;
            uint4 vh = make_uint4(0, 0, 0, 0);
            if (r < valid) vh = gh[r * 16 + c];
            *(uint4*)(smem + SM_AH + r * SAS + c * 16) = vh;
        }
    }
    {
        const uint4* wh = (const uint4*)(g_Whi + layer * DIM * DIM);
        const uint4* wl = (const uint4*)(g_Wlo + layer * DIM * DIM);
        #pragma unroll
        for (int i = tid; i < 2048; i += 128) {
            int r = i >> 4, c = i & 15;
            *(uint4*)(smem + SM_WH + r * SAS + c * 16) = wh[i];
            *(uint4*)(smem + SM_WL + r * SAS + c * 16) = wl[i];
        }
    }
    __syncthreads();

    float acc[16][4];
    #pragma unroll
    for (int j = 0; j < 16; j++)
        #pragma unroll
        for (int q = 0; q < 4; q++) acc[j][q] = 0.f;

    int wm = wid * 16;
    uint32_t a_off = (uint32_t)((wm + (lane & 15)) * SAS + ((lane >> 4) << 3) * 2);
    uint32_t b_off = (uint32_t)(((lane & 7) + ((lane >> 4) << 3)) * SAS + (((lane >> 3) & 1) << 3) * 2);

    for (int kk = 0; kk < 8; kk++) {
        uint32_t kb = kk * 32;
        uint32_t ah[4];
        ldsm4(sb + SM_AH + a_off + kb, ah);
        #pragma unroll
        for (int nt = 0; nt < 8; nt++) {
            uint32_t bh[4], bl[4];
            uint32_t nrow = nt * 16 * SAS;
            ldsm4(sb + SM_WH + nrow + b_off + kb, bh);
            ldsm4(sb + SM_WL + nrow + b_off + kb, bl);
            mma16816(acc[2 * nt],     ah, bh[0], bh[1]);
            mma16816(acc[2 * nt + 1], ah, bh[2], bh[3]);
            mma16816(acc[2 * nt],     ah, bl[0], bl[1]);
            mma16816(acc[2 * nt + 1], ah, bl[2], bl[3]);
        }
    }

    int r0 = m0 + wm + (lane >> 2);
    int cb = (lane & 3) * 2;
    if (r0 < N_NODES) {
        __half* d = g_hw + (long long)r0 * DIM;
        #pragma unroll
        for (int j = 0; j < 16; j++)
            *(__half2*)(d + j * 8 + cb) = __floats2half2_rn(acc[j][0], acc[j][1]);
    }
    if (r0 + 8 < N_NODES) {
        __half* d = g_hw + (long long)(r0 + 8) * DIM;
        #pragma unroll
        for (int j = 0; j < 16; j++)
            *(__half2*)(d + j * 8 + cb) = __floats2half2_rn(acc[j][2], acc[j][3]);
    }
}

// ---------------- SpMM: fp16 gather (4-wide), fused edges, fp32 acc, relu, bf16 out ----
__device__ __forceinline__ void acc_edge(float4& acc, float n, uint2 v) {
    float2 a = h2f2(v.x), b = h2f2(v.y);
    acc.x += n * a.x; acc.y += n * a.y; acc.z += n * b.x; acc.w += n * b.y;
}

__global__ void __launch_bounds__(256) k_spmm(const float* __restrict__ bias) {
    int warp = (blockIdx.x * blockDim.x + threadIdx.x) >> 5;
    int lane = threadIdx.x & 31;
    if (warp >= N_NODES) return;
    int i = warp;

    float di = g_dinv[i];
    float sl = di * di;
    float4 acc;
    {
        uint2 v = ((const uint2*)(g_hw + (long long)i * DIM))[lane];
        float2 a = h2f2(v.x), b = h2f2(v.y);
        acc = make_float4(sl * a.x, sl * a.y, sl * b.x, sl * b.y);
    }

    int p = g_off[i], pe = g_off[i + 1];
    for (; p + 4 <= pe; p += 4) {
        int2 e0 = g_edge[p],     e1 = g_edge[p + 1];
        int2 e2 = g_edge[p + 2], e3 = g_edge[p + 3];
        uint2 v0 = ((const uint2*)(g_hw + (long long)e0.x * DIM))[lane];
        uint2 v1 = ((const uint2*)(g_hw + (long long)e1.x * DIM))[lane];
        uint2 v2 = ((const uint2*)(g_hw + (long long)e2.x * DIM))[lane];
        uint2 v3 = ((const uint2*)(g_hw + (long long)e3.x * DIM))[lane];
        acc_edge(acc, __int_as_float(e0.y), v0);
        acc_edge(acc, __int_as_float(e1.y), v1);
        acc_edge(acc, __int_as_float(e2.y), v2);
        acc_edge(acc, __int_as_float(e3.y), v3);
    }
    for (; p < pe; p++) {
        int2 e = g_edge[p];
        uint2 v = ((const uint2*)(g_hw + (long long)e.x * DIM))[lane];
        acc_edge(acc, __int_as_float(e.y), v);
    }

    float4 bv = ((const float4*)bias)[lane];
    acc.x = fmaxf(acc.x + bv.x, 0.f);
    acc.y = fmaxf(acc.y + bv.y, 0.f);
    acc.z = fmaxf(acc.z + bv.z, 0.f);
    acc.w = fmaxf(acc.w + bv.w, 0.f);

    uint2 ph;
    ph.x = packbf2(acc.x, acc.y);
    ph.y = packbf2(acc.z, acc.w);
    ((uint2*)g_Ahi)[(long long)i * 32 + lane] = ph;
}

// ---------------- global mean pool (partial sums; no atomics) ----------------
__device__ __forceinline__ int lbound(const void* __restrict__ b, int key) {
    int lo = 0, hi = N_NODES;
    while (lo < hi) {
        int mid = (lo + hi) >> 1;
        if (ldidx(b, mid) < key) lo = mid + 1; else hi = mid;
    }
    return lo;
}
__global__ void k_pool(const void* __restrict__ batch) {
    int g = blockIdx.x / PCH;
    int c = blockIdx.x % PCH;
    int t = threadIdx.x;
    int start = lbound(batch, g);
    int end   = lbound(batch, g + 1);
    int len = end - start;
    int rs = start + (int)((long long)len * c / PCH);
    int re = start + (int)((long long)len * (c + 1) / PCH);
    float s = 0.f;
    for (int r = rs; r < re; r++)
        s += __bfloat162float(g_Ahi[(long long)r * DIM + t]);
    g_pool[(c * NGRAPH + g) * DIM + t] = s;
}
__global__ void k_pool_div(const void* __restrict__ batch, float* __restrict__ out) {
    int g = blockIdx.x;
    int t = threadIdx.x;
    float s = 0.f;
    #pragma unroll
    for (int c = 0; c < PCH; c++) s += g_pool[(c * NGRAPH + g) * DIM + t];
    int start = lbound(batch, g);
    int end   = lbound(batch, g + 1);
    float cnt = (float)(end - start);
    if (cnt < 1.f) cnt = 1.f;
    out[g * DIM + t] = s / cnt;
}

// ---------------- launch: gemm0 overlaps k_fill ONLY (both throughput kernels; ------
// ---------------- k_scan stays alone — R13 showed overlap starves it) ---------------
extern "C" void kernel_launch(void* const* d_in, const int* in_sizes, int n_in,
                              void* d_out, int out_size) {
    (void)out_size;
    const float* x = 0; const void* ei = 0; const void* batch = 0;
    const float* W[3] = {0, 0, 0}; const float* b[3] = {0, 0, 0};
    int nw = 0, nb = 0;
    for (int i = 0; i < n_in; i++) {
        int sz = in_sizes[i];
        if      (sz == N_NODES * DIM) x     = (const float*)d_in[i];
        else if (sz == 2 * N_EDGES)   ei    = d_in[i];
        else if (sz == N_NODES)       batch = d_in[i];
        else if (sz == DIM * DIM)     { if (nw < 3) W[nw++] = (const float*)d_in[i]; }
        else if (sz == DIM)           { if (nb < 3) b[nb++] = (const float*)d_in[i]; }
    }
    float* out = (float*)d_out;

    static cudaStream_t s1 = nullptr;
    static cudaEvent_t ev_fork = nullptr, ev_join = nullptr;
    if (!s1) {
        cudaStreamCreateWithFlags(&s1, cudaStreamNonBlocking);
        cudaEventCreateWithFlags(&ev_fork, cudaEventDisableTiming);
        cudaEventCreateWithFlags(&ev_join, cudaEventDisableTiming);
        cudaFuncSetAttribute(k_gemm_mma, cudaFuncAttributeMaxDynamicSharedMemorySize, SM_TOT);
    }

    const int NT = 256;
    int nblk = (N_NODES + NT - 1) / NT;
    int e2blk = (N_EDGES / 2 + NT - 1) / NT;
    int spmm_blocks = (N_NODES * 32 + NT - 1) / NT;
    int gemm_blocks = (N_NODES + 63) / 64;  // 782

    // preprocess; scan runs alone
    k_init<<<nblk, NT>>>((const int*)ei, W[0], W[1], W[2]);
    k_degree<<<e2blk, NT>>>(ei);
    k_scan<<<1, 1024>>>();

    // fork after scan: gemm0 (s1) overlaps k_fill (main) — both throughput kernels
    cudaEventRecord(ev_fork, 0);
    cudaStreamWaitEvent(s1, ev_fork, 0);
    k_gemm_mma<<<gemm_blocks, 128, SM_TOT, s1>>>(0, x);
    cudaEventRecord(ev_join, s1);

    k_fill<<<e2blk, NT>>>(ei);

    cudaStreamWaitEvent(0, ev_join, 0);

    // remaining layers
    k_spmm<<<spmm_blocks, NT>>>(b[0]);
    k_gemm_mma<<<gemm_blocks, 128, SM_TOT>>>(1, nullptr);
    k_spmm<<<spmm_blocks, NT>>>(b[1]);
    k_gemm_mma<<<gemm_blocks, 128, SM_TOT>>>(2, nullptr);
    k_spmm<<<spmm_blocks, NT>>>(b[2]);

    // pool (partial sums)
    k_pool<<<NGRAPH * PCH, DIM>>>(batch);
    k_pool_div<<<NGRAPH, DIM>>>(batch, out);
}